// round 11
// baseline (speedup 1.0000x reference)
#include <cuda_runtime.h>
#include <cstdint>
#include <math.h>

// Problem constants
#define B_   2
#define HQ_  16
#define S_   2048
#define D_   64
#define DV_  128
#define GROUPS 32
#define GROUP_ELEMS 131072
#define PPG 8

// Scratch (no allocations allowed -> device globals)
static __device__ float  g_o[(size_t)B_ * HQ_ * S_ * DV_];   // 33.5MB
static __device__ double g_psum[GROUPS * PPG];
static __device__ double g_psq [GROUPS * PPG];

// ---------------------------------------------------------------------------
__device__ __forceinline__ uint32_t f2tf(float x) {
    uint32_t r;
    asm("cvt.rna.tf32.f32 %0, %1;" : "=r"(r) : "f"(x));
    return r;
}

__device__ __forceinline__ void mma8(float& c0, float& c1, float& c2, float& c3,
                                     uint32_t a0, uint32_t a1, uint32_t a2, uint32_t a3,
                                     uint32_t b0, uint32_t b1) {
    asm volatile(
        "mma.sync.aligned.m16n8k8.row.col.f32.tf32.tf32.f32 "
        "{%0,%1,%2,%3},{%4,%5,%6,%7},{%8,%9},{%0,%1,%2,%3};"
        : "+f"(c0), "+f"(c1), "+f"(c2), "+f"(c3)
        : "r"(a0), "r"(a1), "r"(a2), "r"(a3), "r"(b0), "r"(b1));
}

#define CP16(dst, src) asm volatile("cp.async.cg.shared.global [%0], [%1], 16;" :: "r"(dst), "l"(src))
#define CP_COMMIT()    asm volatile("cp.async.commit_group;")
#define CP_WAIT0()     asm volatile("cp.async.wait_group 0;")

// ---------------------------------------------------------------------------
// Flash attention, BM=128, BN=64, 256 threads = 8 warps x m16 rows x full DV.
//
// Per tile, K and V are repacked from row-major raw buffers into PERMUTED
// layouts so each thread's B-fragment elements are contiguous:
//   K: element (key,d) -> row key (16 float4 chunks),
//      chunk = ((d&3) + 4*(d>>4)) ^ ((key&3)<<2), word = (d>>2)&3
//   V: element (key,dv) -> row dv,
//      chunk = ((key&3) + 4*(key>>4)) ^ ((dv&3)<<2) ^ ((dv>>2)&15),
//      word = (key>>2)&3
// Thread (r,qd) then reads 4x LDS.128 per 8-key n-tile (conflict-free).
//
// Fixed ghost-max m=0 (exact: w = e^s/(sum e^s + 1), logits bounded) -> no
// online max, no O rescale.
//
// smem floats: rawK[0,4096) rawV[4096,12288) Kp[12288,16384) Vp[16384,24576)
// Q staged in Vp during prologue; epilogue staging aliases [0,16384). 96KB.
// ---------------------------------------------------------------------------
__global__ __launch_bounds__(256)
void attn_kernel(const float* __restrict__ q,
                 const float* __restrict__ k,
                 const float* __restrict__ v) {
    extern __shared__ float sm[];
    float* rawK = sm;
    float* rawV = sm + 4096;
    float* Kp   = sm + 12288;
    float* Vp   = sm + 16384;
    float* Ost  = sm;                 // epilogue alias (128x128)

    const int tid  = threadIdx.x;
    const int lane = tid & 31;
    const int wm   = tid >> 5;        // 0..7
    const int r    = lane >> 2;       // 0..7
    const int qd   = lane & 3;        // 0..3
    const unsigned F = 0xffffffffu;

    const int qt = 15 - blockIdx.x;   // heavy tiles first
    const int h  = blockIdx.y;
    const int b  = blockIdx.z;
    const int hp = h >> 1;

    uint32_t smb;
    asm("{ .reg .u64 t; cvta.to.shared.u64 t, %1; cvt.u32.u64 %0, t; }" : "=r"(smb) : "l"(sm));

    const float4* qg = reinterpret_cast<const float4*>(
        q + (((size_t)b * HQ_ + h) * S_ + (size_t)qt * 128) * D_);
    const float4* kg = reinterpret_cast<const float4*>(k + ((size_t)b * HQ_ + h) * S_ * D_);
    const float4* vg = reinterpret_cast<const float4*>(v + ((size_t)b * (HQ_ / 2) + hp) * S_ * DV_);

    // ---- prologue: Q -> Vp area (plain), K0/V0 -> raw (plain) ----
#pragma unroll
    for (int i0 = 0; i0 < 8; i0++) {
        int i = i0 * 256 + tid;
        CP16(smb + 65536u + (uint32_t)i * 16u, qg + i);
    }
#pragma unroll
    for (int i0 = 0; i0 < 4; i0++) {
        int i = i0 * 256 + tid;
        CP16(smb + (uint32_t)i * 16u, kg + i);
    }
#pragma unroll
    for (int i0 = 0; i0 < 8; i0++) {
        int i = i0 * 256 + tid;
        CP16(smb + 16384u + (uint32_t)i * 16u, vg + i);
    }
    CP_COMMIT();
    CP_WAIT0();
    __syncthreads();

    // ---- extract Q A-fragments (scale + RNA tf32) from plain Q in Vp ----
    uint32_t qa[8][4];
    {
        int R0 = (wm * 16 + r) * 64, R1 = R0 + 8 * 64;
#pragma unroll
        for (int kk = 0; kk < 8; kk++) {
            int d0 = kk * 8 + qd;
            qa[kk][0] = f2tf(Vp[R0 + d0] * 0.125f);
            qa[kk][1] = f2tf(Vp[R1 + d0] * 0.125f);
            qa[kk][2] = f2tf(Vp[R0 + d0 + 4] * 0.125f);
            qa[kk][3] = f2tf(Vp[R1 + d0 + 4] * 0.125f);
        }
    }
    __syncthreads();   // Q area (Vp) free for repack

    const int ktmax = 2 * qt + 1;
    const int W0 = qt * 128 + wm * 16;

    float oc[16][4];
#pragma unroll
    for (int j = 0; j < 16; j++) { oc[j][0] = 0.f; oc[j][1] = 0.f; oc[j][2] = 0.f; oc[j][3] = 0.f; }
    float l0 = 1.f, l1 = 1.f;   // ghost logit exp(0)

    for (int t = 0; t <= ktmax; t++) {
        // ---- repack K (RNA tf32) raw -> permuted ----
#pragma unroll
        for (int i0 = 0; i0 < 4; i0++) {
            int j = i0 * 256 + tid;
            int key = j >> 4, c4 = j & 15;
            float4 x = reinterpret_cast<const float4*>(rawK)[j];
            int xr = (key & 3) << 2;
            int base = key * 64 + (c4 & 3) + ((((c4 >> 2) << 2) ^ xr) << 2);
            Kp[base]      = __uint_as_float(f2tf(x.x));
            Kp[base + 4]  = __uint_as_float(f2tf(x.y));
            Kp[base + 8]  = __uint_as_float(f2tf(x.z));
            Kp[base + 12] = __uint_as_float(f2tf(x.w));
        }
        // ---- repack V raw -> permuted (RZ; raw f32 bits fed to mma) ----
#pragma unroll
        for (int i0 = 0; i0 < 8; i0++) {
            int j = i0 * 256 + tid;
            int key = j >> 5, dv4 = j & 31;
            float4 x = reinterpret_cast<const float4*>(rawV)[j];
            int cbase = ((key & 3) + ((key >> 4) << 2)) ^ (dv4 & 15);
            int word = (key >> 2) & 3;
            int dv0 = dv4 << 2;
            Vp[(dv0    ) * 64 + ((cbase      ) << 2) + word] = x.x;
            Vp[(dv0 + 1) * 64 + ((cbase ^ 4  ) << 2) + word] = x.y;
            Vp[(dv0 + 2) * 64 + ((cbase ^ 8  ) << 2) + word] = x.z;
            Vp[(dv0 + 3) * 64 + ((cbase ^ 12 ) << 2) + word] = x.w;
        }
        __syncthreads();   // repack done; raw buffers free

        if (t < ktmax) {
            const float4* kp2 = kg + (size_t)(t + 1) * 1024;
            const float4* vp2 = vg + (size_t)(t + 1) * 2048;
#pragma unroll
            for (int i0 = 0; i0 < 4; i0++) {
                int i = i0 * 256 + tid;
                CP16(smb + (uint32_t)i * 16u, kp2 + i);
            }
#pragma unroll
            for (int i0 = 0; i0 < 8; i0++) {
                int i = i0 * 256 + tid;
                CP16(smb + 16384u + (uint32_t)i * 16u, vp2 + i);
            }
            CP_COMMIT();
        }

        const bool active = (t * 64 <= W0 + 15);
        if (active) {
            // ---- S = Q @ K^T : 8 n-tiles x (4 LDS.128 + 8 mma) ----
            float sc[8][4];
#pragma unroll
            for (int jn = 0; jn < 8; jn++) {
                int keyr = jn * 8 + r;
                const float4* kr = reinterpret_cast<const float4*>(Kp) + keyr * 16 + qd;
                int xr = (keyr & 3) << 2;
                float c0 = 0.f, c1 = 0.f, c2 = 0.f, c3 = 0.f;
#pragma unroll
                for (int i = 0; i < 4; i++) {
                    float4 vv = kr[(4 * i) ^ xr];
                    mma8(c0, c1, c2, c3, qa[2*i][0], qa[2*i][1], qa[2*i][2], qa[2*i][3],
                         __float_as_uint(vv.x), __float_as_uint(vv.y));
                    mma8(c0, c1, c2, c3, qa[2*i+1][0], qa[2*i+1][1], qa[2*i+1][2], qa[2*i+1][3],
                         __float_as_uint(vv.z), __float_as_uint(vv.w));
                }
                sc[jn][0] = c0; sc[jn][1] = c1; sc[jn][2] = c2; sc[jn][3] = c3;
            }

            // ---- ghost softmax, fixed m=0; causal mask on partial tiles ----
            float rs0 = 0.f, rs1 = 0.f;
            if (t * 64 + 63 > W0) {
                int grow0 = W0 + r;
#pragma unroll
                for (int jn = 0; jn < 8; jn++) {
                    int gc = t * 64 + jn * 8 + 2 * qd;
                    sc[jn][0] = (gc     <= grow0    ) ? __expf(sc[jn][0]) : 0.f;
                    sc[jn][1] = (gc + 1 <= grow0    ) ? __expf(sc[jn][1]) : 0.f;
                    sc[jn][2] = (gc     <= grow0 + 8) ? __expf(sc[jn][2]) : 0.f;
                    sc[jn][3] = (gc + 1 <= grow0 + 8) ? __expf(sc[jn][3]) : 0.f;
                    rs0 += sc[jn][0] + sc[jn][1];
                    rs1 += sc[jn][2] + sc[jn][3];
                }
            } else {
#pragma unroll
                for (int jn = 0; jn < 8; jn++) {
                    sc[jn][0] = __expf(sc[jn][0]);
                    sc[jn][1] = __expf(sc[jn][1]);
                    sc[jn][2] = __expf(sc[jn][2]);
                    sc[jn][3] = __expf(sc[jn][3]);
                    rs0 += sc[jn][0] + sc[jn][1];
                    rs1 += sc[jn][2] + sc[jn][3];
                }
            }
            rs0 += __shfl_xor_sync(F, rs0, 1);
            rs0 += __shfl_xor_sync(F, rs0, 2);
            rs1 += __shfl_xor_sync(F, rs1, 1);
            rs1 += __shfl_xor_sync(F, rs1, 2);
            l0 += rs0;
            l1 += rs1;

            // ---- build all P A-fragments (intra-quad shuffles, RNA tf32) ----
            uint32_t pa[8][4];
            {
                const int srcA = (lane & ~3) | (qd >> 1);
                const int srcB = srcA + 2;
                const bool odd = qd & 1;
#pragma unroll
                for (int kk2 = 0; kk2 < 8; kk2++) {
                    float x00 = __shfl_sync(F, sc[kk2][0], srcA);
                    float x01 = __shfl_sync(F, sc[kk2][1], srcA);
                    float x20 = __shfl_sync(F, sc[kk2][2], srcA);
                    float x21 = __shfl_sync(F, sc[kk2][3], srcA);
                    float y00 = __shfl_sync(F, sc[kk2][0], srcB);
                    float y01 = __shfl_sync(F, sc[kk2][1], srcB);
                    float y20 = __shfl_sync(F, sc[kk2][2], srcB);
                    float y21 = __shfl_sync(F, sc[kk2][3], srcB);
                    pa[kk2][0] = f2tf(odd ? x01 : x00);
                    pa[kk2][1] = f2tf(odd ? x21 : x20);
                    pa[kk2][2] = f2tf(odd ? y01 : y00);
                    pa[kk2][3] = f2tf(odd ? y21 : y20);
                }
            }

            // ---- O += P @ V : 16 dv-tiles x (4 LDS.128 + 8 mma) ----
#pragma unroll
            for (int jo = 0; jo < 16; jo++) {
                int dv = jo * 8 + r;
                int X = ((dv & 3) << 2) ^ ((dv >> 2) & 15);
                const float4* vr = reinterpret_cast<const float4*>(Vp) + dv * 16 + (qd ^ (X & 3));
                int xi = X & 12;
#pragma unroll
                for (int i = 0; i < 4; i++) {
                    float4 vv = vr[(4 * i) ^ xi];
                    mma8(oc[jo][0], oc[jo][1], oc[jo][2], oc[jo][3],
                         pa[2*i][0], pa[2*i][1], pa[2*i][2], pa[2*i][3],
                         __float_as_uint(vv.x), __float_as_uint(vv.y));
                    mma8(oc[jo][0], oc[jo][1], oc[jo][2], oc[jo][3],
                         pa[2*i+1][0], pa[2*i+1][1], pa[2*i+1][2], pa[2*i+1][3],
                         __float_as_uint(vv.z), __float_as_uint(vv.w));
                }
            }
        }
        if (t < ktmax) CP_WAIT0();
        __syncthreads();   // compute done with Kp/Vp; raw(t+1) visible
    }

    // ---- epilogue: /l, stage 128x128 to smem, coalesced store ----
    {
        float inv0 = 1.f / l0, inv1 = 1.f / l1;
        int row0 = wm * 16 + r, row1 = row0 + 8;
        int s0 = (r & 3) << 3;
#pragma unroll
        for (int jo = 0; jo < 16; jo++) {
            int c = jo * 8 + 2 * qd;
            int cs = c ^ s0;
            *reinterpret_cast<float2*>(&Ost[(row0 << 7) + cs]) =
                make_float2(oc[jo][0] * inv0, oc[jo][1] * inv0);
            *reinterpret_cast<float2*>(&Ost[(row1 << 7) + cs]) =
                make_float2(oc[jo][2] * inv1, oc[jo][3] * inv1);
        }
    }
    __syncthreads();
    {
        float4* op = reinterpret_cast<float4*>(
            g_o + (((size_t)b * HQ_ + h) * S_ + (size_t)qt * 128) * DV_);
        const float4* Os4 = reinterpret_cast<const float4*>(Ost);
#pragma unroll
        for (int i0 = 0; i0 < 16; i0++) {
            int i = i0 * 256 + tid;
            int row = i >> 5, c4 = i & 31;
            op[i] = Os4[(row << 5) + (c4 ^ ((row & 3) << 1))];
        }
    }
}

// ---------------------------------------------------------------------------
__device__ __forceinline__ float compute_lam(const float* lq1, const float* lk1,
                                             const float* lq2, const float* lk2) {
    float s1 = 0.f, s2 = 0.f;
    for (int j = 0; j < 64; j++) { s1 += lq1[j] * lk1[j]; s2 += lq2[j] * lk2[j]; }
    return expf(s1) - expf(s2) + 0.8f;
}

// Group g = b*16 + hp*2 + (s>=1024): contiguous 131072-elem chunk of
// diff = o[2hp] - lam*o[2hp+1]. Deterministic fixed-slot partials, fp32 inner.
__global__ void stats_partial_kernel(const float* __restrict__ lq1, const float* __restrict__ lk1,
                                     const float* __restrict__ lq2, const float* __restrict__ lk2) {
    __shared__ float s_lam;
    if (threadIdx.x == 0) s_lam = compute_lam(lq1, lk1, lq2, lk2);
    __syncthreads();
    float lam = s_lam;

    int g = blockIdx.x >> 3, p = blockIdx.x & 7;
    int b = g >> 4, gg = g & 15, hp = gg >> 1, half = gg & 1;
    const float4* o0 = reinterpret_cast<const float4*>(
        g_o + (((size_t)(b * 16 + 2 * hp)) * S_ + (size_t)half * 1024) * DV_) + p * 4096;
    const float4* o1 = o0 + (size_t)S_ * DV_ / 4;
    float sum = 0.f, sq = 0.f;
    for (int j = threadIdx.x; j < 4096; j += 256) {
        float4 a = o0[j], c = o1[j];
        float d0 = a.x - lam * c.x, d1 = a.y - lam * c.y;
        float d2 = a.z - lam * c.z, d3 = a.w - lam * c.w;
        sum += d0 + d1 + d2 + d3;
        sq  += d0 * d0 + d1 * d1 + d2 * d2 + d3 * d3;
    }
    __shared__ double ssum[256], ssq[256];
    ssum[threadIdx.x] = (double)sum; ssq[threadIdx.x] = (double)sq;
    __syncthreads();
    for (int st = 128; st > 0; st >>= 1) {
        if (threadIdx.x < st) {
            ssum[threadIdx.x] += ssum[threadIdx.x + st];
            ssq[threadIdx.x]  += ssq[threadIdx.x + st];
        }
        __syncthreads();
    }
    if (threadIdx.x == 0) {
        g_psum[blockIdx.x] = ssum[0];
        g_psq[blockIdx.x]  = ssq[0];
    }
}

// Fused final stats + diff + normalize + affine + 0.2x. Group constant per block.
__global__ void normalize_kernel(const float* __restrict__ lq1, const float* __restrict__ lk1,
                                 const float* __restrict__ lq2, const float* __restrict__ lk2,
                                 const float* __restrict__ gw, const float* __restrict__ gb,
                                 float* __restrict__ out) {
    int i4 = blockIdx.x * 256 + threadIdx.x;
    int dv4 = i4 & 31;
    int s   = (i4 >> 5) & 2047;
    int hp  = (i4 >> 16) & 7;
    int b   = i4 >> 19;

    __shared__ float s_lam, s_mean, s_istd;
    if (threadIdx.x == 0) {
        s_lam = compute_lam(lq1, lk1, lq2, lk2);
        int g = b * 16 + hp * 2 + (s >> 10);
        double sum = 0.0, sq = 0.0;
        for (int p = 0; p < PPG; p++) { sum += g_psum[g * PPG + p]; sq += g_psq[g * PPG + p]; }
        double mean = sum / (double)GROUP_ELEMS;
        double var  = sq / (double)GROUP_ELEMS - mean * mean;
        s_mean = (float)mean;
        s_istd = (float)(1.0 / sqrt(var + 1e-5));
    }
    __syncthreads();
    float lam = s_lam, mean = s_mean, istd = s_istd;

    int c = hp * 128 + (s >> 4);
    float wgt = gw[c] * istd * 0.2f;
    float bia = (gb[c] - mean * istd * gw[c]) * 0.2f;

    const float4* o0 = reinterpret_cast<const float4*>(g_o) +
        (((size_t)(b * 16 + 2 * hp)) * S_ + s) * (DV_ / 4) + dv4;
    const float4* o1 = o0 + (size_t)S_ * DV_ / 4;
    float4 a = *o0, cc = *o1;
    float4 res;
    res.x = (a.x - lam * cc.x) * wgt + bia;
    res.y = (a.y - lam * cc.y) * wgt + bia;
    res.z = (a.z - lam * cc.z) * wgt + bia;
    res.w = (a.w - lam * cc.w) * wgt + bia;
    reinterpret_cast<float4*>(out)[i4] = res;
}

// ---------------------------------------------------------------------------
extern "C" void kernel_launch(void* const* d_in, const int* in_sizes, int n_in,
                              void* d_out, int out_size) {
    const float* q   = (const float*)d_in[0];
    const float* k   = (const float*)d_in[1];
    const float* v   = (const float*)d_in[2];
    const float* lq1 = (const float*)d_in[3];
    const float* lk1 = (const float*)d_in[4];
    const float* lq2 = (const float*)d_in[5];
    const float* lk2 = (const float*)d_in[6];
    const float* gw  = (const float*)d_in[7];
    const float* gb  = (const float*)d_in[8];
    float* out = (float*)d_out;

    cudaFuncSetAttribute(attn_kernel, cudaFuncAttributeMaxDynamicSharedMemorySize, 98304);

    attn_kernel<<<dim3(S_ / 128, HQ_, B_), 256, 98304>>>(q, k, v);
    stats_partial_kernel<<<GROUPS * PPG, 256>>>(lq1, lk1, lq2, lk2);
    normalize_kernel<<<(B_ * (HQ_ / 2) * S_ * DV_) / 1024, 256>>>(lq1, lk1, lq2, lk2, gw, gb, out);
}

// round 13
// speedup vs baseline: 1.1641x; 1.1641x over previous
#include <cuda_runtime.h>
#include <cstdint>
#include <math.h>

// Problem constants
#define B_   2
#define HQ_  16
#define S_   2048
#define D_   64
#define DV_  128
#define GROUPS 32
#define GROUP_ELEMS 131072
#define PPG 8

// Scratch (no allocations allowed -> device globals)
static __device__ float  g_o[(size_t)B_ * HQ_ * S_ * DV_];    // 33.5MB
static __device__ float  g_kp[(size_t)B_ * HQ_ * S_ * D_];    // 16MB permuted K (tf32)
static __device__ float  g_vp[(size_t)B_ * (HQ_/2) * S_ * DV_]; // 16MB permuted V
static __device__ double g_psum[GROUPS * PPG];
static __device__ double g_psq [GROUPS * PPG];

// ---------------------------------------------------------------------------
__device__ __forceinline__ uint32_t f2tf(float x) {
    uint32_t r;
    asm("cvt.rna.tf32.f32 %0, %1;" : "=r"(r) : "f"(x));
    return r;
}

__device__ __forceinline__ void mma8(float& c0, float& c1, float& c2, float& c3,
                                     uint32_t a0, uint32_t a1, uint32_t a2, uint32_t a3,
                                     uint32_t b0, uint32_t b1) {
    asm volatile(
        "mma.sync.aligned.m16n8k8.row.col.f32.tf32.tf32.f32 "
        "{%0,%1,%2,%3},{%4,%5,%6,%7},{%8,%9},{%0,%1,%2,%3};"
        : "+f"(c0), "+f"(c1), "+f"(c2), "+f"(c3)
        : "r"(a0), "r"(a1), "r"(a2), "r"(a3), "r"(b0), "r"(b1));
}

#define CP16(dst, src) asm volatile("cp.async.cg.shared.global [%0], [%1], 16;" :: "r"(dst), "l"(src))
#define CP_COMMIT()    asm volatile("cp.async.commit_group;")
#define CP_WAIT0()     asm volatile("cp.async.wait_group 0;")

// ---------------------------------------------------------------------------
// Prep: K -> g_kp (RNA tf32, permuted 64x64 tiles), V -> g_vp (permuted
// 64x128 tiles). Layout formulas identical to R11's in-smem repack
// (numerically verified). One thread per raw float4.
// ---------------------------------------------------------------------------
__global__ __launch_bounds__(256)
void prep_kernel(const float* __restrict__ k, const float* __restrict__ v) {
    int bx = blockIdx.x;
    if (bx < 4096) {
        int j = bx * 256 + threadIdx.x;              // float4 index into k
        int head = j >> 15;                          // 32768 f4 per head
        int jj = j & 32767;
        int keyg = jj >> 4, c4 = jj & 15;
        int t = keyg >> 6, key = keyg & 63;
        float4 x = reinterpret_cast<const float4*>(k)[j];
        float* dst = g_kp + ((size_t)(head * 32 + t)) * 4096;
        int xr = (key & 3) << 2;
        int base = key * 64 + (c4 & 3) + ((((c4 >> 2) << 2) ^ xr) << 2);
        dst[base]      = __uint_as_float(f2tf(x.x));
        dst[base + 4]  = __uint_as_float(f2tf(x.y));
        dst[base + 8]  = __uint_as_float(f2tf(x.z));
        dst[base + 12] = __uint_as_float(f2tf(x.w));
    } else {
        int j = (bx - 4096) * 256 + threadIdx.x;     // float4 index into v
        int vhead = j >> 16;                         // 65536 f4 per v-head
        int jj = j & 65535;
        int keyg = jj >> 5, dv4 = jj & 31;
        int t = keyg >> 6, key = keyg & 63;
        float4 x = reinterpret_cast<const float4*>(v)[j];
        float* dst = g_vp + ((size_t)(vhead * 32 + t)) * 8192;
        int cbase = ((key & 3) + ((key >> 4) << 2)) ^ (dv4 & 15);
        int word = (key >> 2) & 3;
        int dv0 = dv4 << 2;
        dst[(dv0    ) * 64 + ((cbase      ) << 2) + word] = x.x;
        dst[(dv0 + 1) * 64 + ((cbase ^ 4 ) << 2) + word] = x.y;
        dst[(dv0 + 2) * 64 + ((cbase ^ 8 ) << 2) + word] = x.z;
        dst[(dv0 + 3) * 64 + ((cbase ^ 12) << 2) + word] = x.w;
    }
}

// ---------------------------------------------------------------------------
// Flash attention, BM=128, BN=64, 256 threads = 8 warps x m16 rows x full DV.
// K/V arrive ALREADY permuted+converted from g_kp/g_vp via contiguous
// cp.async (no in-loop repack, no barrier-split phases).
// B-fragments: 4x LDS.128 per 8-key/8-dv tile (R11-verified mappings).
// Fixed ghost-max m=0 (exact). l reduced across lanes once after the loop.
// smem floats: K 2x4096 @0 | V 2x8192 @8192; Q staged @16384 (V buf1);
// epilogue staging aliases [0,16384). 96KB dynamic.
// ---------------------------------------------------------------------------
__global__ __launch_bounds__(256)
void attn_kernel(const float* __restrict__ q) {
    extern __shared__ float sm[];

    const int tid  = threadIdx.x;
    const int lane = tid & 31;
    const int wm   = tid >> 5;        // 0..7
    const int r    = lane >> 2;       // 0..7
    const int qd   = lane & 3;        // 0..3
    const unsigned F = 0xffffffffu;

    const int qt = 15 - blockIdx.x;   // heavy tiles first
    const int h  = blockIdx.y;
    const int b  = blockIdx.z;
    const int hp = h >> 1;
    const int head  = b * HQ_ + h;
    const int vhead = b * (HQ_ / 2) + hp;

    uint32_t smb;
    asm("{ .reg .u64 t; cvta.to.shared.u64 t, %1; cvt.u32.u64 %0, t; }" : "=r"(smb) : "l"(sm));

    const float4* qg = reinterpret_cast<const float4*>(
        q + (((size_t)head) * S_ + (size_t)qt * 128) * D_);
    const float4* kpg = reinterpret_cast<const float4*>(g_kp + ((size_t)head * 32) * 4096);
    const float4* vpg = reinterpret_cast<const float4*>(g_vp + ((size_t)vhead * 32) * 8192);

    // ---- prologue: Q -> V buf1 area (plain), K0/V0 tiles (contiguous) ----
#pragma unroll
    for (int i0 = 0; i0 < 8; i0++) {
        int i = i0 * 256 + tid;
        CP16(smb + 65536u + (uint32_t)i * 16u, qg + i);
    }
#pragma unroll
    for (int i0 = 0; i0 < 4; i0++) {
        int i = i0 * 256 + tid;
        CP16(smb + (uint32_t)i * 16u, kpg + i);
    }
#pragma unroll
    for (int i0 = 0; i0 < 8; i0++) {
        int i = i0 * 256 + tid;
        CP16(smb + 32768u + (uint32_t)i * 16u, vpg + i);
    }
    CP_COMMIT();
    CP_WAIT0();
    __syncthreads();

    // ---- extract Q A-fragments (scale + RNA tf32) from plain Q ----
    uint32_t qa[8][4];
    {
        const float* Qs = sm + 16384;
        int R0 = (wm * 16 + r) * 64, R1 = R0 + 512;
#pragma unroll
        for (int kk = 0; kk < 8; kk++) {
            int d0 = kk * 8 + qd;
            qa[kk][0] = f2tf(Qs[R0 + d0] * 0.125f);
            qa[kk][1] = f2tf(Qs[R1 + d0] * 0.125f);
            qa[kk][2] = f2tf(Qs[R0 + d0 + 4] * 0.125f);
            qa[kk][3] = f2tf(Qs[R1 + d0 + 4] * 0.125f);
        }
    }
    __syncthreads();   // Q area (V buf1) free for prefetch

    const int ktmax = 2 * qt + 1;
    const int W0 = qt * 128 + wm * 16;

    float oc[16][4];
#pragma unroll
    for (int j = 0; j < 16; j++) { oc[j][0] = 0.f; oc[j][1] = 0.f; oc[j][2] = 0.f; oc[j][3] = 0.f; }
    float lp0 = 0.f, lp1 = 0.f;    // per-lane partial softmax sums

    for (int t = 0; t <= ktmax; t++) {
        const int cur = t & 1;
        if (t > 0) { CP_WAIT0(); __syncthreads(); }

        // prefetch next tile into the other buffer (contiguous cp.async)
        if (t < ktmax) {
            const int nxt = cur ^ 1;
            const float4* kp2 = kpg + (size_t)(t + 1) * 1024;
            const float4* vp2 = vpg + (size_t)(t + 1) * 2048;
            const uint32_t kdst = smb + (uint32_t)nxt * 16384u;
            const uint32_t vdst = smb + 32768u + (uint32_t)nxt * 32768u;
#pragma unroll
            for (int i0 = 0; i0 < 4; i0++) {
                int i = i0 * 256 + tid;
                CP16(kdst + (uint32_t)i * 16u, kp2 + i);
            }
#pragma unroll
            for (int i0 = 0; i0 < 8; i0++) {
                int i = i0 * 256 + tid;
                CP16(vdst + (uint32_t)i * 16u, vp2 + i);
            }
            CP_COMMIT();
        }

        const float* Kp = sm + cur * 4096;
        const float* Vp = sm + 8192 + cur * 8192;

        const bool active = (t * 64 <= W0 + 15);
        if (active) {
            // ---- S = Q @ K^T : 8 n-tiles x (4 LDS.128 + 8 mma) ----
            float sc[8][4];
#pragma unroll
            for (int jn = 0; jn < 8; jn++) {
                int keyr = jn * 8 + r;
                const float4* kr = reinterpret_cast<const float4*>(Kp) + keyr * 16 + qd;
                int xr = (keyr & 3) << 2;
                float c0 = 0.f, c1 = 0.f, c2 = 0.f, c3 = 0.f;
#pragma unroll
                for (int i = 0; i < 4; i++) {
                    float4 vv = kr[(4 * i) ^ xr];
                    mma8(c0, c1, c2, c3, qa[2*i][0], qa[2*i][1], qa[2*i][2], qa[2*i][3],
                         __float_as_uint(vv.x), __float_as_uint(vv.y));
                    mma8(c0, c1, c2, c3, qa[2*i+1][0], qa[2*i+1][1], qa[2*i+1][2], qa[2*i+1][3],
                         __float_as_uint(vv.z), __float_as_uint(vv.w));
                }
                sc[jn][0] = c0; sc[jn][1] = c1; sc[jn][2] = c2; sc[jn][3] = c3;
            }

            // ---- ghost softmax, fixed m=0; causal mask on partial tiles ----
            if (t * 64 + 63 > W0) {
                int grow0 = W0 + r;
#pragma unroll
                for (int jn = 0; jn < 8; jn++) {
                    int gc = t * 64 + jn * 8 + 2 * qd;
                    sc[jn][0] = (gc     <= grow0    ) ? __expf(sc[jn][0]) : 0.f;
                    sc[jn][1] = (gc + 1 <= grow0    ) ? __expf(sc[jn][1]) : 0.f;
                    sc[jn][2] = (gc     <= grow0 + 8) ? __expf(sc[jn][2]) : 0.f;
                    sc[jn][3] = (gc + 1 <= grow0 + 8) ? __expf(sc[jn][3]) : 0.f;
                    lp0 += sc[jn][0] + sc[jn][1];
                    lp1 += sc[jn][2] + sc[jn][3];
                }
            } else {
#pragma unroll
                for (int jn = 0; jn < 8; jn++) {
                    sc[jn][0] = __expf(sc[jn][0]);
                    sc[jn][1] = __expf(sc[jn][1]);
                    sc[jn][2] = __expf(sc[jn][2]);
                    sc[jn][3] = __expf(sc[jn][3]);
                    lp0 += sc[jn][0] + sc[jn][1];
                    lp1 += sc[jn][2] + sc[jn][3];
                }
            }

            // ---- build P A-fragments (intra-quad shuffles, RNA tf32) ----
            uint32_t pa[8][4];
            {
                const int srcA = (lane & ~3) | (qd >> 1);
                const int srcB = srcA + 2;
                const bool odd = qd & 1;
#pragma unroll
                for (int kk2 = 0; kk2 < 8; kk2++) {
                    float x00 = __shfl_sync(F, sc[kk2][0], srcA);
                    float x01 = __shfl_sync(F, sc[kk2][1], srcA);
                    float x20 = __shfl_sync(F, sc[kk2][2], srcA);
                    float x21 = __shfl_sync(F, sc[kk2][3], srcA);
                    float y00 = __shfl_sync(F, sc[kk2][0], srcB);
                    float y01 = __shfl_sync(F, sc[kk2][1], srcB);
                    float y20 = __shfl_sync(F, sc[kk2][2], srcB);
                    float y21 = __shfl_sync(F, sc[kk2][3], srcB);
                    pa[kk2][0] = f2tf(odd ? x01 : x00);
                    pa[kk2][1] = f2tf(odd ? x21 : x20);
                    pa[kk2][2] = f2tf(odd ? y01 : y00);
                    pa[kk2][3] = f2tf(odd ? y21 : y20);
                }
            }

            // ---- O += P @ V : 16 dv-tiles x (4 LDS.128 + 8 mma) ----
#pragma unroll
            for (int jo = 0; jo < 16; jo++) {
                int dv = jo * 8 + r;
                int X = ((dv & 3) << 2) ^ ((dv >> 2) & 15);
                const float4* vr = reinterpret_cast<const float4*>(Vp) + dv * 16 + (qd ^ (X & 3));
                int xi = X & 12;
#pragma unroll
                for (int i = 0; i < 4; i++) {
                    float4 vv = vr[(4 * i) ^ xi];
                    mma8(oc[jo][0], oc[jo][1], oc[jo][2], oc[jo][3],
                         pa[2*i][0], pa[2*i][1], pa[2*i][2], pa[2*i][3],
                         __float_as_uint(vv.x), __float_as_uint(vv.y));
                    mma8(oc[jo][0], oc[jo][1], oc[jo][2], oc[jo][3],
                         pa[2*i+1][0], pa[2*i+1][1], pa[2*i+1][2], pa[2*i+1][3],
                         __float_as_uint(vv.z), __float_as_uint(vv.w));
                }
            }
        }
    }

    // ---- final l reduce (once), epilogue staging + coalesced store ----
    float l0, l1;
    {
        lp0 += __shfl_xor_sync(F, lp0, 1);
        lp0 += __shfl_xor_sync(F, lp0, 2);
        lp1 += __shfl_xor_sync(F, lp1, 1);
        lp1 += __shfl_xor_sync(F, lp1, 2);
        l0 = 1.f + lp0;   // ghost logit exp(0)
        l1 = 1.f + lp1;
    }
    __syncthreads();
    {
        float* Ost = sm;
        float inv0 = 1.f / l0, inv1 = 1.f / l1;
        int row0 = wm * 16 + r, row1 = row0 + 8;
        int s0 = (r & 3) << 3;
#pragma unroll
        for (int jo = 0; jo < 16; jo++) {
            int c = jo * 8 + 2 * qd;
            int cs = c ^ s0;
            *reinterpret_cast<float2*>(&Ost[(row0 << 7) + cs]) =
                make_float2(oc[jo][0] * inv0, oc[jo][1] * inv0);
            *reinterpret_cast<float2*>(&Ost[(row1 << 7) + cs]) =
                make_float2(oc[jo][2] * inv1, oc[jo][3] * inv1);
        }
    }
    __syncthreads();
    {
        float4* op = reinterpret_cast<float4*>(
            g_o + (((size_t)head) * S_ + (size_t)qt * 128) * DV_);
        const float4* Os4 = reinterpret_cast<const float4*>(sm);
#pragma unroll
        for (int i0 = 0; i0 < 16; i0++) {
            int i = i0 * 256 + tid;
            int row = i >> 5, c4 = i & 31;
            op[i] = Os4[(row << 5) + (c4 ^ ((row & 3) << 1))];
        }
    }
}

// ---------------------------------------------------------------------------
__device__ __forceinline__ float compute_lam(const float* lq1, const float* lk1,
                                             const float* lq2, const float* lk2) {
    float s1 = 0.f, s2 = 0.f;
    for (int j = 0; j < 64; j++) { s1 += lq1[j] * lk1[j]; s2 += lq2[j] * lk2[j]; }
    return expf(s1) - expf(s2) + 0.8f;
}

// Group g = b*16 + hp*2 + (s>=1024): contiguous 131072-elem chunk of
// diff = o[2hp] - lam*o[2hp+1]. Deterministic fixed-slot partials, fp32 inner.
__global__ void stats_partial_kernel(const float* __restrict__ lq1, const float* __restrict__ lk1,
                                     const float* __restrict__ lq2, const float* __restrict__ lk2) {
    __shared__ float s_lam;
    if (threadIdx.x == 0) s_lam = compute_lam(lq1, lk1, lq2, lk2);
    __syncthreads();
    float lam = s_lam;

    int g = blockIdx.x >> 3, p = blockIdx.x & 7;
    int b = g >> 4, gg = g & 15, hp = gg >> 1, half = gg & 1;
    const float4* o0 = reinterpret_cast<const float4*>(
        g_o + (((size_t)(b * 16 + 2 * hp)) * S_ + (size_t)half * 1024) * DV_) + p * 4096;
    const float4* o1 = o0 + (size_t)S_ * DV_ / 4;
    float sum = 0.f, sq = 0.f;
    for (int j = threadIdx.x; j < 4096; j += 256) {
        float4 a = o0[j], c = o1[j];
        float d0 = a.x - lam * c.x, d1 = a.y - lam * c.y;
        float d2 = a.z - lam * c.z, d3 = a.w - lam * c.w;
        sum += d0 + d1 + d2 + d3;
        sq  += d0 * d0 + d1 * d1 + d2 * d2 + d3 * d3;
    }
    __shared__ double ssum[256], ssq[256];
    ssum[threadIdx.x] = (double)sum; ssq[threadIdx.x] = (double)sq;
    __syncthreads();
    for (int st = 128; st > 0; st >>= 1) {
        if (threadIdx.x < st) {
            ssum[threadIdx.x] += ssum[threadIdx.x + st];
            ssq[threadIdx.x]  += ssq[threadIdx.x + st];
        }
        __syncthreads();
    }
    if (threadIdx.x == 0) {
        g_psum[blockIdx.x] = ssum[0];
        g_psq[blockIdx.x]  = ssq[0];
    }
}

// Fused final stats + diff + normalize + affine + 0.2x. Group constant per block.
__global__ void normalize_kernel(const float* __restrict__ lq1, const float* __restrict__ lk1,
                                 const float* __restrict__ lq2, const float* __restrict__ lk2,
                                 const float* __restrict__ gw, const float* __restrict__ gb,
                                 float* __restrict__ out) {
    int i4 = blockIdx.x * 256 + threadIdx.x;
    int dv4 = i4 & 31;
    int s   = (i4 >> 5) & 2047;
    int hp  = (i4 >> 16) & 7;
    int b   = i4 >> 19;

    __shared__ float s_lam, s_mean, s_istd;
    if (threadIdx.x == 0) {
        s_lam = compute_lam(lq1, lk1, lq2, lk2);
        int g = b * 16 + hp * 2 + (s >> 10);
        double sum = 0.0, sq = 0.0;
        for (int p = 0; p < PPG; p++) { sum += g_psum[g * PPG + p]; sq += g_psq[g * PPG + p]; }
        double mean = sum / (double)GROUP_ELEMS;
        double var  = sq / (double)GROUP_ELEMS - mean * mean;
        s_mean = (float)mean;
        s_istd = (float)(1.0 / sqrt(var + 1e-5));
    }
    __syncthreads();
    float lam = s_lam, mean = s_mean, istd = s_istd;

    int c = hp * 128 + (s >> 4);
    float wgt = gw[c] * istd * 0.2f;
    float bia = (gb[c] - mean * istd * gw[c]) * 0.2f;

    const float4* o0 = reinterpret_cast<const float4*>(g_o) +
        (((size_t)(b * 16 + 2 * hp)) * S_ + s) * (DV_ / 4) + dv4;
    const float4* o1 = o0 + (size_t)S_ * DV_ / 4;
    float4 a = *o0, cc = *o1;
    float4 res;
    res.x = (a.x - lam * cc.x) * wgt + bia;
    res.y = (a.y - lam * cc.y) * wgt + bia;
    res.z = (a.z - lam * cc.z) * wgt + bia;
    res.w = (a.w - lam * cc.w) * wgt + bia;
    reinterpret_cast<float4*>(out)[i4] = res;
}

// ---------------------------------------------------------------------------
extern "C" void kernel_launch(void* const* d_in, const int* in_sizes, int n_in,
                              void* d_out, int out_size) {
    const float* q   = (const float*)d_in[0];
    const float* k   = (const float*)d_in[1];
    const float* v   = (const float*)d_in[2];
    const float* lq1 = (const float*)d_in[3];
    const float* lk1 = (const float*)d_in[4];
    const float* lq2 = (const float*)d_in[5];
    const float* lk2 = (const float*)d_in[6];
    const float* gw  = (const float*)d_in[7];
    const float* gb  = (const float*)d_in[8];
    float* out = (float*)d_out;

    cudaFuncSetAttribute(attn_kernel, cudaFuncAttributeMaxDynamicSharedMemorySize, 98304);

    prep_kernel<<<8192, 256>>>(k, v);
    attn_kernel<<<dim3(S_ / 128, HQ_, B_), 256, 98304>>>(q);
    stats_partial_kernel<<<GROUPS * PPG, 256>>>(lq1, lk1, lq2, lk2);
    normalize_kernel<<<(B_ * (HQ_ / 2) * S_ * DV_) / 1024, 256>>>(lq1, lk1, lq2, lk2, gw, gb, out);
}